// round 1
// baseline (speedup 1.0000x reference)
#include <cuda_runtime.h>

// RoPE_90847148245015
// feats: [B=16, C=256, H=128, W=128] fp32   (d_in[0])
// R:     [H=128, C=256, C=256] fp32          (d_in[1])  block-sparse rotation
// out:   [B=16, C=256, H=128, W=128] fp32
//
// out[b,2k,  h,w] = R[h,2k,2k]    *f[b,2k,h,w] + R[h,2k,2k+1]*f[b,2k+1,h,w]
// out[b,2k+1,h,w] = R[h,2k+1,2k+1]*f[b,2k+1,h,w] + R[h,2k+1,2k]*f[b,2k,h,w]
// (all other R entries are exactly 0 by construction)
//
// One thread = one (b, k, h, w4): two float4 loads, two float4 stores.
// Warp = one (b,k,h) row -> R coefficient loads are warp-uniform.

__global__ __launch_bounds__(256) void rope_rot_kernel(
    const float* __restrict__ feats,
    const float* __restrict__ R,
    float* __restrict__ out)
{
    const int idx = blockIdx.x * 256 + threadIdx.x;
    // idx layout: [b:4][k:7][h:7][w4:5]
    const int w4 = idx & 31;
    const int h  = (idx >> 5) & 127;
    const int k  = (idx >> 12) & 127;
    const int b  = idx >> 19;

    // R[h, 2k, 2k] ; stride: h*256*256 + row*256 + col
    const int rbase = (h << 16) + (k << 9) + (k << 1);  // h*65536 + 2k*256 + 2k
    const float c  = __ldg(R + rbase);        // cos   = R[h,2k,2k] (== R[h,2k+1,2k+1])
    const float se = __ldg(R + rbase + 1);    // -sin  = R[h,2k,2k+1]
    const float so = __ldg(R + rbase + 256);  // +sin  = R[h,2k+1,2k]
    // exact cos for odd row (identical value by construction, read for bitwise safety)
    const float co = __ldg(R + rbase + 257);  // R[h,2k+1,2k+1]

    // feats/out as float4: plane stride H*W/4 = 4096, row stride W/4 = 32
    const int base = (((b << 8) + (k << 1)) << 12) + (h << 5) + w4;  // (b*256+2k)*4096 + h*32 + w4

    const float4* __restrict__ f4 = reinterpret_cast<const float4*>(feats);
    float4* __restrict__ o4 = reinterpret_cast<float4*>(out);

    const float4 fe = __ldg(f4 + base);
    const float4 fo = __ldg(f4 + base + 4096);

    float4 oe, oo;
    oe.x = fmaf(c, fe.x, se * fo.x);
    oe.y = fmaf(c, fe.y, se * fo.y);
    oe.z = fmaf(c, fe.z, se * fo.z);
    oe.w = fmaf(c, fe.w, se * fo.w);
    oo.x = fmaf(co, fo.x, so * fe.x);
    oo.y = fmaf(co, fo.y, so * fe.y);
    oo.z = fmaf(co, fo.z, so * fe.z);
    oo.w = fmaf(co, fo.w, so * fe.w);

    o4[base]        = oe;
    o4[base + 4096] = oo;
}

extern "C" void kernel_launch(void* const* d_in, const int* in_sizes, int n_in,
                              void* d_out, int out_size) {
    const float* feats = (const float*)d_in[0];
    const float* R     = (const float*)d_in[1];
    float* out         = (float*)d_out;

    // total float4 work items: B*K*H*(W/4) = 16*128*128*32 = 8,388,608
    const int total = 16 * 128 * 128 * 32;
    rope_rot_kernel<<<total / 256, 256>>>(feats, R, out);
}

// round 2
// speedup vs baseline: 1.0211x; 1.0211x over previous
#include <cuda_runtime.h>

// RoPE_90847148245015 — block-sparse RoPE rotation, pure streaming kernel.
// feats: [B=16, C=256, H=128, W=128] fp32   (d_in[0])
// R:     [H=128, C=256, C=256] fp32          (d_in[1])
// out:   [B=16, C=256, H=128, W=128] fp32
//
// out[b,2k,  h,w] = R[h,2k,2k]    *f[b,2k,h,w] + R[h,2k,2k+1]*f[b,2k+1,h,w]
// out[b,2k+1,h,w] = R[h,2k+1,2k+1]*f[b,2k+1,h,w] + R[h,2k+1,2k]*f[b,2k,h,w]
//
// R2 changes vs R1:
//  - unroll x2 over batch (b and b+8): 4 independent LDG.128 in flight per
//    thread instead of 2, same 4 warp-uniform R loads (R depends on h,k only)
//  - __ldcs on feats, __stcs on out (no reuse -> evict-first, keep L2 for R)

__global__ __launch_bounds__(256) void rope_rot_kernel(
    const float* __restrict__ feats,
    const float* __restrict__ R,
    float* __restrict__ out)
{
    const int idx = blockIdx.x * 256 + threadIdx.x;
    // idx layout: [b3:3][k:7][h:7][w4:5]  (b in {b3, b3+8})
    const int w4 = idx & 31;
    const int h  = (idx >> 5) & 127;
    const int k  = (idx >> 12) & 127;
    const int b3 = idx >> 19;          // 0..7

    // R[h, 2k, 2k] ; element stride: h*65536 + row*256 + col
    const int rbase = (h << 16) + (k << 9) + (k << 1);
    const float ce = __ldg(R + rbase);        // cos  (even row)
    const float se = __ldg(R + rbase + 1);    // -sin
    const float so = __ldg(R + rbase + 256);  // +sin
    const float co = __ldg(R + rbase + 257);  // cos  (odd row)

    // float4 indexing: plane stride 4096, row stride 32, batch stride 256*4096
    const int base0 = (((b3 << 8) + (k << 1)) << 12) + (h << 5) + w4;
    const int base1 = base0 + (8 << 20);      // b3+8:  8*256*4096

    const float4* __restrict__ f4 = reinterpret_cast<const float4*>(feats);
    float4* __restrict__ o4 = reinterpret_cast<float4*>(out);

    // 4 independent streaming loads, front-batched for MLP
    const float4 fe0 = __ldcs(f4 + base0);
    const float4 fo0 = __ldcs(f4 + base0 + 4096);
    const float4 fe1 = __ldcs(f4 + base1);
    const float4 fo1 = __ldcs(f4 + base1 + 4096);

    float4 oe0, oo0, oe1, oo1;
    oe0.x = fmaf(ce, fe0.x, se * fo0.x);
    oe0.y = fmaf(ce, fe0.y, se * fo0.y);
    oe0.z = fmaf(ce, fe0.z, se * fo0.z);
    oe0.w = fmaf(ce, fe0.w, se * fo0.w);
    oo0.x = fmaf(co, fo0.x, so * fe0.x);
    oo0.y = fmaf(co, fo0.y, so * fe0.y);
    oo0.z = fmaf(co, fo0.z, so * fe0.z);
    oo0.w = fmaf(co, fo0.w, so * fe0.w);

    oe1.x = fmaf(ce, fe1.x, se * fo1.x);
    oe1.y = fmaf(ce, fe1.y, se * fo1.y);
    oe1.z = fmaf(ce, fe1.z, se * fo1.z);
    oe1.w = fmaf(ce, fe1.w, se * fo1.w);
    oo1.x = fmaf(co, fo1.x, so * fe1.x);
    oo1.y = fmaf(co, fo1.y, so * fe1.y);
    oo1.z = fmaf(co, fo1.z, so * fe1.z);
    oo1.w = fmaf(co, fo1.w, so * fe1.w);

    __stcs(o4 + base0,        oe0);
    __stcs(o4 + base0 + 4096, oo0);
    __stcs(o4 + base1,        oe1);
    __stcs(o4 + base1 + 4096, oo1);
}

extern "C" void kernel_launch(void* const* d_in, const int* in_sizes, int n_in,
                              void* d_out, int out_size) {
    const float* feats = (const float*)d_in[0];
    const float* R     = (const float*)d_in[1];
    float* out         = (float*)d_out;

    // threads: (B/2)*K*H*(W/4) = 8*128*128*32 = 4,194,304
    const int total = 8 * 128 * 128 * 32;
    rope_rot_kernel<<<total / 256, 256>>>(feats, R, out);
}